// round 2
// baseline (speedup 1.0000x reference)
#include <cuda_runtime.h>

// ---------------------------------------------------------------------------
// 2-layer LSTM (B=8, T=2048, D_IN=256, H=512), relu cell nonlinearity.
// Persistent pipelined kernel: layer0 computes t=s while layer1 computes
// t=s-1 (2049 macro-steps). Weights live in SMEM (transposed), recurrent
// h state double-buffered in device globals (transposed [j][b]), grid-wide
// release/acquire barrier per macro-step. Inner dot products use packed
// fp32 fma.rn.f32x2 (Blackwell FFMA2) for 2x fp32 throughput.
// ---------------------------------------------------------------------------

#define GRID    128
#define NB0      64          // layer-0 blocks; rest are layer-1
#define THREADS 256
#define TSTEPS 2048
#define HID     512
#define BATCH     8
#define DIN     256

// output layout: h2 [B,T,H] | hh [2,B,H] | cc [2,B,H]
#define OUT_HH  (BATCH * TSTEPS * HID)              // 8388608
#define OUT_CC  (OUT_HH + 2 * BATCH * HID)          // 8396800

// SMEM layout (floats)
#define SM_W      0                       // 1024*33  (layer0 uses 768*33)
#define SM_IN     (1024 * 33)             // 1024*12  (pad 12, float4-aligned)
#define SM_PART   (SM_IN + 1024 * 12)     // 8 warps * 32 rows * 8 b
#define SM_GATES  (SM_PART + 2048)        // 256
#define SM_BIAS   (SM_GATES + 256)        // 32
#define SM_C      (SM_BIAS + 32)          // 64
#define SM_FLOATS (SM_C + 64)             // 48480 floats = 193920 bytes
#define SM_BYTES  (SM_FLOATS * 4)

__device__ unsigned g_count;
__device__ unsigned g_gen;
__device__ float    g_h0[2 * HID * BATCH];   // layer0 hidden (== layer1 input), [par][j][b]
__device__ float    g_h2[2 * HID * BATCH];   // layer1 hidden, [par][j][b]

__global__ void init_kernel() {
    int t = threadIdx.x;
    if (t == 0) { g_count = 0; g_gen = 0; }
    for (int i = t; i < 2 * HID * BATCH; i += blockDim.x) {
        g_h0[i] = 0.0f;
        g_h2[i] = 0.0f;
    }
}

typedef unsigned long long u64;

__device__ __forceinline__ u64 pack2(float lo, float hi) {
    u64 r;
    asm("mov.b64 %0, {%1, %2};" : "=l"(r) : "f"(lo), "f"(hi));
    return r;
}
__device__ __forceinline__ void ffma2(u64& acc, u64 a, u64 b) {
    asm("fma.rn.f32x2 %0, %1, %2, %3;" : "=l"(acc) : "l"(a), "l"(b), "l"(acc));
}
__device__ __forceinline__ float2 unpack2(u64 v) {
    float2 f;
    asm("mov.b64 {%0, %1}, %2;" : "=f"(f.x), "=f"(f.y) : "l"(v));
    return f;
}
__device__ __forceinline__ float sigmoidf_(float x) {
    return 1.0f / (1.0f + __expf(-x));
}
// gpu-scope release add (arrival) and acquire load (poll)
__device__ __forceinline__ void arrive_release(unsigned* p) {
    asm volatile("red.release.gpu.global.add.u32 [%0], 1;" :: "l"(p) : "memory");
}
__device__ __forceinline__ unsigned ld_acquire(const unsigned* p) {
    unsigned v;
    asm volatile("ld.acquire.gpu.global.u32 %0, [%1];" : "=r"(v) : "l"(p) : "memory");
    return v;
}
__device__ __forceinline__ unsigned atom_inc_acqrel(unsigned* p) {
    unsigned v;
    asm volatile("atom.acq_rel.gpu.global.add.u32 %0, [%1], 1;" : "=r"(v) : "l"(p) : "memory");
    return v;
}
__device__ __forceinline__ void st_release(unsigned* p, unsigned v) {
    asm volatile("st.release.gpu.global.u32 [%0], %1;" :: "l"(p), "r"(v) : "memory");
}

extern __shared__ float sm[];

__global__ void __launch_bounds__(THREADS, 1)
lstm_kernel(const float* __restrict__ x,
            const float* __restrict__ w0w, const float* __restrict__ w0b,
            const float* __restrict__ u0w, const float* __restrict__ u0b,
            const float* __restrict__ w1w, const float* __restrict__ w1b,
            const float* __restrict__ u1w, const float* __restrict__ u1b,
            float* __restrict__ out)
{
    float* W_s     = sm + SM_W;      // [k][33] transposed, row = lane
    float* in_s    = sm + SM_IN;     // [k][12] (b in 0..7)
    float* part_s  = sm + SM_PART;   // [warp][row][b]
    float* gates_s = sm + SM_GATES;  // [g*64 + u*8 + b]
    float* bias_s  = sm + SM_BIAS;   // [row]
    float* c_s     = sm + SM_C;      // [u*8 + b], persistent cell state

    const int tid  = threadIdx.x;
    const int bx   = blockIdx.x;
    const bool is0 = (bx < NB0);
    const int ub   = is0 ? bx * 8 : (bx - NB0) * 8;   // unit base (8 units/block)
    const int L    = is0 ? (DIN + HID) : (2 * HID);   // 768 | 1024

    // ---- one-time: load weight slice transposed into SMEM ----
    // local row r = g*8 + u  ->  global gate row gid = g*HID + ub + u
    for (int r = 0; r < 32; ++r) {
        int g = r >> 3, u = r & 7;
        int gid = g * HID + ub + u;
        if (is0) {
            for (int k = tid; k < DIN; k += THREADS)
                W_s[k * 33 + r] = w0w[gid * DIN + k];
            for (int k = tid; k < HID; k += THREADS)
                W_s[(DIN + k) * 33 + r] = u0w[gid * HID + k];
            if (tid == 0) bias_s[r] = w0b[gid] + u0b[gid];
        } else {
            for (int k = tid; k < HID; k += THREADS)
                W_s[k * 33 + r] = w1w[gid * HID + k];
            for (int k = tid; k < HID; k += THREADS)
                W_s[(HID + k) * 33 + r] = u1w[gid * HID + k];
            if (tid == 0) bias_s[r] = w1b[gid] + u1b[gid];
        }
    }
    if (tid < 64) c_s[tid] = 0.0f;
    __syncthreads();

    const int warp   = tid >> 5;
    const int lane   = tid & 31;      // lane == local gate row
    const int kchunk = L / 8;         // 8 warps split the dot
    const int kbeg   = warp * kchunk;
    const int kend   = kbeg + kchunk;

    for (int s = 0; s <= TSTEPS; ++s) {
        const int par = s & 1;
        const int np  = par ^ 1;
        const int t   = is0 ? s : (s - 1);
        const bool active = is0 ? (s < TSTEPS) : (s >= 1);

        if (active) {
            // ---- stage step inputs into in_s[k][b] ----
            if (is0) {
                // x_t: [b][d] -> in_s[d][b]
                for (int i = tid; i < BATCH * DIN; i += THREADS) {
                    int b = i >> 8, d = i & 255;
                    in_s[d * 12 + b] = __ldg(&x[((size_t)b * TSTEPS + t) * DIN + d]);
                }
                // h0_prev (transposed global, linear copy)
                for (int i = tid; i < BATCH * HID; i += THREADS) {
                    float v = __ldcv(&g_h0[par * HID * BATCH + i]);
                    in_s[(DIN + (i >> 3)) * 12 + (i & 7)] = v;
                }
            } else {
                for (int i = tid; i < BATCH * HID; i += THREADS) {
                    float v1 = __ldcv(&g_h0[par * HID * BATCH + i]);  // h1_t
                    float v2 = __ldcv(&g_h2[par * HID * BATCH + i]);  // h2_{t-1}
                    in_s[(i >> 3) * 12 + (i & 7)]         = v1;
                    in_s[(HID + (i >> 3)) * 12 + (i & 7)] = v2;
                }
            }
            __syncthreads();

            // ---- dot products: lane = row, warp = k-chunk, 8 b in f32x2 pairs ----
            u64 a01 = 0, a23 = 0, a45 = 0, a67 = 0;
            #pragma unroll 4
            for (int k = kbeg; k < kend; ++k) {
                float uw = W_s[k * 33 + lane];
                u64 u2 = pack2(uw, uw);
                const float4 ha = *(const float4*)&in_s[k * 12];
                const float4 hb = *(const float4*)&in_s[k * 12 + 4];
                ffma2(a01, u2, pack2(ha.x, ha.y));
                ffma2(a23, u2, pack2(ha.z, ha.w));
                ffma2(a45, u2, pack2(hb.x, hb.y));
                ffma2(a67, u2, pack2(hb.z, hb.w));
            }
            {
                float2 f01 = unpack2(a01), f23 = unpack2(a23);
                float2 f45 = unpack2(a45), f67 = unpack2(a67);
                float* p = &part_s[(warp * 32 + lane) * 8];
                *(float4*)(p)     = make_float4(f01.x, f01.y, f23.x, f23.y);
                *(float4*)(p + 4) = make_float4(f45.x, f45.y, f67.x, f67.y);
            }
            __syncthreads();

            // ---- reduce 8 warps: thread tid = row*8 + b ----
            {
                int row = tid >> 3, b = tid & 7;
                float acc = bias_s[row];
                #pragma unroll
                for (int w = 0; w < 8; ++w)
                    acc += part_s[(w * 32 + row) * 8 + b];
                gates_s[tid] = acc;   // == [g*64 + u*8 + b]
            }
            __syncthreads();

            // ---- pointwise LSTM cell: 64 threads (u,b) ----
            if (tid < 64) {
                float iv = sigmoidf_(gates_s[tid]);
                float fv = sigmoidf_(gates_s[64 + tid]);
                float gv = tanhf(gates_s[128 + tid]);
                float ov = sigmoidf_(gates_s[192 + tid]);
                float c = fv * c_s[tid] + iv * gv;
                c_s[tid] = c;
                float h = ov * fmaxf(c, 0.0f);   // relu cell nonlinearity
                int u = tid >> 3, b = tid & 7;
                int j = ub + u;
                if (is0) {
                    g_h0[np * HID * BATCH + j * 8 + b] = h;
                    if (t == TSTEPS - 1) {
                        out[OUT_HH + b * HID + j] = h;
                        out[OUT_CC + b * HID + j] = c;
                    }
                } else {
                    g_h2[np * HID * BATCH + j * 8 + b] = h;
                    out[((size_t)b * TSTEPS + t) * HID + j] = h;
                    if (t == TSTEPS - 1) {
                        out[OUT_HH + BATCH * HID + b * HID + j] = h;
                        out[OUT_CC + BATCH * HID + b * HID + j] = c;
                    }
                }
            }
        }

        // ---- grid-wide barrier (release/acquire, nanosleep backoff) ----
        __syncthreads();
        if (tid == 0) {
            unsigned target = (unsigned)(s + 1);
            unsigned prev   = atom_inc_acqrel(&g_count);
            if (prev + 1u == target * GRID) {
                st_release(&g_gen, target);
            } else {
                while (ld_acquire(&g_gen) < target) { __nanosleep(64); }
            }
        }
        __syncthreads();
    }
}

extern "C" void kernel_launch(void* const* d_in, const int* in_sizes, int n_in,
                              void* d_out, int out_size)
{
    (void)in_sizes; (void)n_in; (void)out_size;
    static int attr_ok = -1;
    if (attr_ok < 0) {
        cudaError_t e = cudaFuncSetAttribute(
            lstm_kernel, cudaFuncAttributeMaxDynamicSharedMemorySize, SM_BYTES);
        attr_ok = (e == cudaSuccess) ? 1 : 0;
        (void)cudaGetLastError();   // clear any sticky error
    }

    const float* x   = (const float*)d_in[0];
    const float* w0w = (const float*)d_in[1];
    const float* w0b = (const float*)d_in[2];
    const float* u0w = (const float*)d_in[3];
    const float* u0b = (const float*)d_in[4];
    const float* w1w = (const float*)d_in[5];
    const float* w1b = (const float*)d_in[6];
    const float* u1w = (const float*)d_in[7];
    const float* u1b = (const float*)d_in[8];
    float* out = (float*)d_out;

    init_kernel<<<1, 256>>>();
    lstm_kernel<<<GRID, THREADS, SM_BYTES>>>(x, w0w, w0b, u0w, u0b,
                                             w1w, w1b, u1w, u1b, out);
}

// round 3
// speedup vs baseline: 1.4711x; 1.4711x over previous
#include <cuda_runtime.h>

// ---------------------------------------------------------------------------
// 2-layer LSTM (B=8, T=2048, D_IN=256, H=512), relu cell nonlinearity.
// 4-group pipelined persistent design:
//   G2 (16 blk): wx0[t] = W0 x[t] + b0   (no deps, streams ahead)
//   G0 (32 blk): h0[t]  = cell(wx0[t] + U0 h0[t-1])
//   G3 (32 blk): wx1[t] = W1 h0[t] + b1  (1 step behind G0)
//   G1 (32 blk): h2[t]  = cell(wx1[t] + U1 h2[t-1])  -> output
// Weights persist in REGISTERS (4 rows x 16 k per thread). Ring buffers in
// L2 (__device__ arrays, depth 8). Per-group monotonic counters with
// red.release / ld.acquire — no central grid barrier.
// ---------------------------------------------------------------------------

typedef unsigned long long u64;
typedef unsigned u32;

#define TSTEPS 2048
#define HID    512
#define BATCH  8
#define DIN    256
#define DEPTH  8

#define NB_G2 16
#define NB_G0 32
#define NB_G3 32
#define NB_G1 32
#define NBLK  112
#define NTHR  512

#define OUT_HH (BATCH * TSTEPS * HID)
#define OUT_CC (OUT_HH + 2 * BATCH * HID)

// SMEM float offsets
#define IN_OFF    0
#define PART_OFF  4096
#define GATES_OFF (4096 + 10240)
#define C_OFF     (GATES_OFF + 1024)
#define SM_FLOATS (C_OFF + 128)
#define SM_BYTES  (SM_FLOATS * 4)

// counters: 0=G2, 1=G0, 2=G3, 3=G1
__device__ u32   g_cnt[4];
__device__ float g_h0ring[DEPTH * HID * BATCH];
__device__ float g_h2ring[DEPTH * HID * BATCH];
__device__ float g_wx0ring[DEPTH * 4 * HID * BATCH];
__device__ float g_wx1ring[DEPTH * 4 * HID * BATCH];

__global__ void init_kernel() {
    int i = blockIdx.x * blockDim.x + threadIdx.x;
    if (i < 4) g_cnt[i] = 0;
    for (int k = i; k < DEPTH * HID * BATCH; k += gridDim.x * blockDim.x) {
        g_h0ring[k] = 0.0f;
        g_h2ring[k] = 0.0f;
    }
}

__device__ __forceinline__ u64 packdup(float w) {
    u64 r;
    asm("mov.b64 %0, {%1, %1};" : "=l"(r) : "f"(w));
    return r;
}
__device__ __forceinline__ void ffma2(u64& d, u64 a, u64 b) {
    asm("fma.rn.f32x2 %0, %1, %2, %3;" : "=l"(d) : "l"(a), "l"(b), "l"(d));
}
__device__ __forceinline__ u64 add2(u64 a, u64 b) {
    u64 d;
    asm("add.rn.f32x2 %0, %1, %2;" : "=l"(d) : "l"(a), "l"(b));
    return d;
}
__device__ __forceinline__ float2 unpk(u64 v) {
    float2 f;
    asm("mov.b64 {%0, %1}, %2;" : "=f"(f.x), "=f"(f.y) : "l"(v));
    return f;
}
__device__ __forceinline__ u32 ld_acquire(const u32* p) {
    u32 v;
    asm volatile("ld.acquire.gpu.global.u32 %0, [%1];" : "=r"(v) : "l"(p) : "memory");
    return v;
}
__device__ __forceinline__ void red_release(u32* p) {
    asm volatile("red.release.gpu.global.add.u32 [%0], 1;" :: "l"(p) : "memory");
}
__device__ __forceinline__ float sigmoidf_(float x) {
    return 1.0f / (1.0f + __expf(-x));
}

// GRP: 0=wx0 proj (128 rows, k=256), 1=rec L0 (64 rows, k=512),
//      2=wx1 proj (64 rows, k=512), 3=rec L1 (64 rows, k=512)
template <int GRP>
__device__ __forceinline__ void run_group(
    const float* __restrict__ x,
    const float* __restrict__ W,
    const float* __restrict__ bA, const float* __restrict__ bB,
    float* __restrict__ out,
    float* __restrict__ sm, int blk, int tid)
{
    constexpr bool ISREC  = (GRP == 1) || (GRP == 3);
    constexpr int  NROWS  = (GRP == 0) ? 128 : 64;
    constexpr int  KLEN   = (GRP == 0) ? 256 : 512;
    constexpr int  UNITS  = NROWS / 4;
    constexpr int  NSLICE = KLEN / 32;
    constexpr int  NE     = (GRP == 0) ? 2 : 1;     // reduce entries per thread

    float* in_s    = sm + IN_OFF;     // [k][8b]
    float* part_s  = sm + PART_OFF;   // [slice][row(stride 10)]
    float* gates_s = sm + GATES_OFF;  // [row][b]
    float* c_s     = sm + C_OFF;      // [unit][b]

    const int ub     = blk * UNITS;
    const int warp   = tid >> 5;
    const int lane   = tid & 31;
    const int kslice = warp % NSLICE;
    const int rowset = warp / NSLICE;
    const int rowgrp = lane & 15;
    const int khalf  = lane >> 4;
    const int kbase  = kslice * 32 + khalf * 16;
    const int rl0    = rowset * 64 + rowgrp * 4;

    // ---- one-time: weights into registers (4 rows x 16 k) ----
    float wreg[4][16];
    #pragma unroll
    for (int r = 0; r < 4; ++r) {
        int rl  = rl0 + r;
        int gid = (rl / UNITS) * HID + ub + (rl % UNITS);
        #pragma unroll
        for (int kk = 0; kk < 16; ++kk)
            wreg[r][kk] = __ldg(&W[(size_t)gid * KLEN + kbase + kk]);
    }

    // ---- one-time: bias (proj) preload for the reduce thread(s) ----
    float biasv[NE];
    if (!ISREC) {
        #pragma unroll
        for (int e = 0; e < NE; ++e) {
            int idx = tid + e * 512;
            int rl  = idx >> 3;
            int gid = (rl / UNITS) * HID + ub + (rl % UNITS);
            biasv[e] = __ldg(&bA[gid]) + __ldg(&bB[gid]);
        }
    }
    if (ISREC && tid < 128) c_s[tid] = 0.0f;
    __syncthreads();

    for (int t = 0; t < TSTEPS; ++t) {
        const int slot = t & (DEPTH - 1);

        // ---- poll dependencies (threads 0..2 in parallel) ----
        int cidx[3] = {0, 0, 0};
        u32 cthr[3] = {0, 0, 0};
        if (GRP == 0) {
            if (t >= DEPTH) { cidx[0] = 1; cthr[0] = NB_G0 * (u32)(t - DEPTH + 1); }
        } else if (GRP == 1) {
            cidx[0] = 0; cthr[0] = NB_G2 * (u32)(t + 1);
            if (t >= 1)     { cidx[1] = 1; cthr[1] = NB_G0 * (u32)t; }
            if (t >= DEPTH) { cidx[2] = 2; cthr[2] = NB_G3 * (u32)(t - DEPTH + 1); }
        } else if (GRP == 2) {
            cidx[0] = 1; cthr[0] = NB_G0 * (u32)(t + 1);
            if (t >= DEPTH) { cidx[1] = 3; cthr[1] = NB_G1 * (u32)(t - DEPTH + 1); }
        } else {
            cidx[0] = 2; cthr[0] = NB_G3 * (u32)(t + 1);
            if (t >= 1) { cidx[1] = 3; cthr[1] = NB_G1 * (u32)t; }
        }
        if (tid < 3 && cthr[tid] > 0) {
            while (ld_acquire(&g_cnt[cidx[tid]]) < cthr[tid]) __nanosleep(32);
        }
        __syncthreads();

        // ---- stage step input into in_s[k][b] ----
        if (GRP == 0) {
            int b = tid >> 6, k4 = (tid & 63) * 4;
            const float4 v = __ldcg((const float4*)&x[((size_t)b * TSTEPS + t) * DIN + k4]);
            in_s[(k4 + 0) * 8 + b] = v.x;
            in_s[(k4 + 1) * 8 + b] = v.y;
            in_s[(k4 + 2) * 8 + b] = v.z;
            in_s[(k4 + 3) * 8 + b] = v.w;
        } else {
            const float* ring = (GRP == 3) ? g_h2ring : g_h0ring;
            const int rslot = (GRP == 2) ? slot : ((t + DEPTH - 1) & (DEPTH - 1));
            const float* src = ring + rslot * HID * BATCH + tid * 8;
            float4 a = __ldcg((const float4*)src);
            float4 b = __ldcg((const float4*)(src + 4));
            *(float4*)&in_s[tid * 8]     = a;
            *(float4*)&in_s[tid * 8 + 4] = b;
        }

        // ---- prefetch wx value for the reduce thread (recurrence only) ----
        float addv = 0.0f;
        if (ISREC) {
            int rl = tid >> 3, b = tid & 7;
            int gid = (rl >> 4) * HID + ub + (rl & 15);
            const float* wxr = (GRP == 1) ? g_wx0ring : g_wx1ring;
            addv = __ldcg(&wxr[slot * 4 * HID * BATCH + gid * 8 + b]);
        }
        __syncthreads();

        // ---- inner dot: 4 rows x 16 k x 8 batch per thread ----
        u64 acc[4][4];
        #pragma unroll
        for (int r = 0; r < 4; ++r)
            #pragma unroll
            for (int p = 0; p < 4; ++p) acc[r][p] = 0;

        #pragma unroll
        for (int kk = 0; kk < 16; ++kk) {
            const float* ip = &in_s[(kbase + kk) * 8];
            u64 i0 = *(const u64*)(ip + 0);
            u64 i1 = *(const u64*)(ip + 2);
            u64 i2 = *(const u64*)(ip + 4);
            u64 i3 = *(const u64*)(ip + 6);
            #pragma unroll
            for (int r = 0; r < 4; ++r) {
                u64 w2 = packdup(wreg[r][kk]);
                ffma2(acc[r][0], w2, i0);
                ffma2(acc[r][1], w2, i1);
                ffma2(acc[r][2], w2, i2);
                ffma2(acc[r][3], w2, i3);
            }
        }

        // ---- khalf pair reduce + write partials ----
        #pragma unroll
        for (int r = 0; r < 4; ++r)
            #pragma unroll
            for (int p = 0; p < 4; ++p) {
                u64 o = __shfl_xor_sync(0xFFFFFFFFu, acc[r][p], 16);
                acc[r][p] = add2(acc[r][p], o);
            }
        if (khalf == 0) {
            #pragma unroll
            for (int r = 0; r < 4; ++r) {
                float* pp = &part_s[kslice * NROWS * 10 + (rl0 + r) * 10];
                #pragma unroll
                for (int p = 0; p < 4; ++p)
                    *(float2*)(pp + 2 * p) = unpk(acc[r][p]);
            }
        }
        __syncthreads();

        // ---- final reduce across k-slices ----
        #pragma unroll
        for (int e = 0; e < NE; ++e) {
            int idx = tid + e * 512;
            int rl = idx >> 3, b = idx & 7;
            float s = ISREC ? addv : biasv[e];
            #pragma unroll
            for (int w = 0; w < NSLICE; ++w)
                s += part_s[w * NROWS * 10 + rl * 10 + b];
            if (ISREC) {
                gates_s[idx] = s;
            } else {
                int gid = (rl / UNITS) * HID + ub + (rl % UNITS);
                float* wxr = (GRP == 0) ? g_wx0ring : g_wx1ring;
                __stcg(&wxr[slot * 4 * HID * BATCH + gid * 8 + b], s);
            }
        }

        // ---- pointwise LSTM cell (recurrence groups) ----
        if (ISREC) {
            __syncthreads();
            if (tid < UNITS * 8) {   // 128
                float iv = sigmoidf_(gates_s[tid]);
                float fv = sigmoidf_(gates_s[128 + tid]);
                float gv = tanhf(gates_s[256 + tid]);
                float ov = sigmoidf_(gates_s[384 + tid]);
                float c = fv * c_s[tid] + iv * gv;
                c_s[tid] = c;
                float h = ov * fmaxf(c, 0.0f);
                int u = tid >> 3, b = tid & 7, j = ub + u;
                float* hr = (GRP == 1) ? g_h0ring : g_h2ring;
                __stcg(&hr[slot * HID * BATCH + j * 8 + b], h);
                if (GRP == 3)
                    out[((size_t)b * TSTEPS + t) * HID + j] = h;
                if (t == TSTEPS - 1) {
                    int L = (GRP == 1) ? 0 : 1;
                    out[OUT_HH + L * BATCH * HID + b * HID + j] = h;
                    out[OUT_CC + L * BATCH * HID + b * HID + j] = c;
                }
            }
        }

        __syncthreads();
        if (tid == 0) red_release(&g_cnt[GRP]);
    }
}

extern __shared__ float smem_dyn[];

__global__ void __launch_bounds__(NTHR, 1)
lstm4_kernel(const float* __restrict__ x,
             const float* __restrict__ w0w, const float* __restrict__ w0b,
             const float* __restrict__ u0w, const float* __restrict__ u0b,
             const float* __restrict__ w1w, const float* __restrict__ w1b,
             const float* __restrict__ u1w, const float* __restrict__ u1b,
             float* __restrict__ out)
{
    const int tid = threadIdx.x;
    const int bx  = blockIdx.x;
    if (bx < NB_G2)
        run_group<0>(x, w0w, w0b, u0b, out, smem_dyn, bx, tid);
    else if (bx < NB_G2 + NB_G0)
        run_group<1>(x, u0w, nullptr, nullptr, out, smem_dyn, bx - NB_G2, tid);
    else if (bx < NB_G2 + NB_G0 + NB_G3)
        run_group<2>(x, w1w, w1b, u1b, out, smem_dyn, bx - NB_G2 - NB_G0, tid);
    else
        run_group<3>(x, u1w, nullptr, nullptr, out, smem_dyn,
                     bx - NB_G2 - NB_G0 - NB_G3, tid);
}

extern "C" void kernel_launch(void* const* d_in, const int* in_sizes, int n_in,
                              void* d_out, int out_size)
{
    (void)in_sizes; (void)n_in; (void)out_size;
    static int attr_done = 0;
    if (!attr_done) {
        cudaFuncSetAttribute(lstm4_kernel,
                             cudaFuncAttributeMaxDynamicSharedMemorySize, SM_BYTES);
        attr_done = 1;
        (void)cudaGetLastError();
    }

    const float* x   = (const float*)d_in[0];
    const float* w0w = (const float*)d_in[1];
    const float* w0b = (const float*)d_in[2];
    const float* u0w = (const float*)d_in[3];
    const float* u0b = (const float*)d_in[4];
    const float* w1w = (const float*)d_in[5];
    const float* w1b = (const float*)d_in[6];
    const float* u1w = (const float*)d_in[7];
    const float* u1b = (const float*)d_in[8];
    float* out = (float*)d_out;

    init_kernel<<<64, 256>>>();
    lstm4_kernel<<<NBLK, NTHR, SM_BYTES>>>(x, w0w, w0b, u0w, u0b,
                                           w1w, w1b, u1w, u1b, out);
}